// round 6
// baseline (speedup 1.0000x reference)
#include <cuda_runtime.h>
#include <cstdint>

// ---------------- problem / tile constants ----------------
#define MB      8192
#define NGATE   1024
#define BM      128          // CTA M tile
#define NJ      64           // gate-local cols per CTA (virtual N = 256)
#define BK      32           // K per stage
#define NKT     64           // 2048 / 32
#define STAGES  3
#define THREADS 256

#define A_STAGE_FLOATS (128 * 32)                 // 4096
#define B_STAGE_FLOATS (256 * 32)                 // 8192
#define STAGE_FLOATS   (A_STAGE_FLOATS + B_STAGE_FLOATS)
#define SMEM_DYN       (STAGES * STAGE_FLOATS * 4)   // 147456 B

__device__ __forceinline__ uint32_t smem_u32(const void* p) {
    return (uint32_t)__cvta_generic_to_shared(p);
}
__device__ __forceinline__ void cp16(uint32_t dst, const void* src) {
    asm volatile("cp.async.cg.shared.global [%0], [%1], 16;\n" :: "r"(dst), "l"(src));
}
__device__ __forceinline__ void cp_commit() { asm volatile("cp.async.commit_group;\n"); }
template <int N>
__device__ __forceinline__ void cp_wait() {
    asm volatile("cp.async.wait_group %0;\n" :: "n"(N));
}
__device__ __forceinline__ uint32_t sw128(uint32_t off) {
    return off ^ ((off >> 3) & 0x70);
}
__device__ __forceinline__ void mma_tf32(float* d, const uint32_t* a, const uint32_t* b) {
    asm volatile(
        "mma.sync.aligned.m16n8k8.row.col.f32.tf32.tf32.f32 "
        "{%0,%1,%2,%3}, {%4,%5,%6,%7}, {%8,%9}, {%0,%1,%2,%3};"
        : "+f"(d[0]), "+f"(d[1]), "+f"(d[2]), "+f"(d[3])
        : "r"(a[0]), "r"(a[1]), "r"(a[2]), "r"(a[3]), "r"(b[0]), "r"(b[1]));
}
__device__ __forceinline__ float tanh_fast(float x) {
    float y;
    asm("tanh.approx.f32 %0, %1;" : "=f"(y) : "f"(x));
    return y;
}
__device__ __forceinline__ float sigmoid_fast(float x) {
    return 0.5f * tanh_fast(0.5f * x) + 0.5f;
}

// ---------------- kernel ----------------
// CTA: 128 rows x 64 gate-local cols of all 4 gates (virtual 128x256).
// Warps 2(m) x 4(n); warp tile 64 rows x 16 gate-local cols (64 virtual).
__global__ void __launch_bounds__(THREADS, 1)
lstm_mma_kernel(const float* __restrict__ e_t,
                const float* __restrict__ h_prev,
                const float* __restrict__ c_prev,
                const float* __restrict__ W_x,
                const float* __restrict__ b_x,
                const float* __restrict__ W_h,
                const float* __restrict__ b_h,
                const float* __restrict__ b_extra,
                float* __restrict__ out)
{
    extern __shared__ float smf[];

    const int tid  = threadIdx.x;
    const int warp = tid >> 5;
    const int lane = tid & 31;
    const int gid  = lane >> 2;     // group id 0..7
    const int tg   = lane & 3;      // thread-in-group
    const int wm   = warp >> 2;     // 0..1 -> rows wm*64
    const int wn   = warp & 3;      // 0..3 -> gate-local cols wn*16
    const int m0   = blockIdx.y * BM;
    const int j0   = blockIdx.x * NJ;

    // ---- stage loader ----
    auto load_stage = [&](int kt, int stg) {
        const int kk = kt * BK;
        const float* __restrict__ Asrc = (kk < 1024) ? e_t : h_prev;
        const float* __restrict__ Wsrc = (kk < 1024) ? W_x : W_h;
        const int kloc = kk & 1023;
        const uint32_t As = smem_u32(smf + stg * STAGE_FLOATS);
        const uint32_t Bs = As + A_STAGE_FLOATS * 4;
        // A: 128 rows x 8 x 16B -> 4 per thread
        #pragma unroll
        for (int i = 0; i < 4; i++) {
            int c = tid + i * THREADS;
            int row = c >> 3, c16 = c & 7;
            cp16(As + sw128((uint32_t)(row * 128 + c16 * 16)),
                 Asrc + (size_t)(m0 + row) * 1024 + kloc + c16 * 4);
        }
        // B: 256 vrows (vr = g*64 + l) x 8 x 16B -> 8 per thread
        #pragma unroll
        for (int i = 0; i < 8; i++) {
            int c = tid + i * THREADS;
            int vr = c >> 3, c16 = c & 7;
            int g = vr >> 6, l = vr & 63;
            cp16(Bs + sw128((uint32_t)(vr * 128 + c16 * 16)),
                 Wsrc + (size_t)(g * NGATE + j0 + l) * 1024 + kloc + c16 * 4);
        }
    };

    // acc[m_frag][gate][n_frag][elem]
    float acc[4][4][2][4];
    #pragma unroll
    for (int i = 0; i < 4; i++)
        #pragma unroll
        for (int g = 0; g < 4; g++)
            #pragma unroll
            for (int nf = 0; nf < 2; nf++)
                #pragma unroll
                for (int e = 0; e < 4; e++) acc[i][g][nf][e] = 0.0f;

    load_stage(0, 0); cp_commit();
    load_stage(1, 1); cp_commit();

    const uint32_t key = (uint32_t)gid << 4;

    for (int kt = 0; kt < NKT; kt++) {
        if (kt + 1 < NKT) cp_wait<1>(); else cp_wait<0>();
        __syncthreads();                    // data visible + prior-iter reads done

        if (kt + 2 < NKT) {
            load_stage(kt + 2, (kt + 2) % STAGES);
            cp_commit();
        }

        const int stg = kt % STAGES;
        const float* As = smf + stg * STAGE_FLOATS;
        const float* Bs = As + A_STAGE_FLOATS;

        #pragma unroll
        for (int ks = 0; ks < 4; ks++) {
            const uint32_t cx = ((uint32_t)(ks * 32 + tg * 4)) ^ key;
            uint32_t a[4][4], b[4][2][2];
            #pragma unroll
            for (int i = 0; i < 4; i++) {
                const uint32_t r0 = (uint32_t)((wm * 64 + i * 16 + gid) * 128) + cx;
                a[i][0] = __float_as_uint(As[ r0             >> 2]);
                a[i][1] = __float_as_uint(As[(r0 + 1024)     >> 2]);
                a[i][2] = __float_as_uint(As[(r0 ^ 16)       >> 2]);
                a[i][3] = __float_as_uint(As[((r0 + 1024) ^ 16) >> 2]);
            }
            #pragma unroll
            for (int g = 0; g < 4; g++)
                #pragma unroll
                for (int nf = 0; nf < 2; nf++) {
                    const uint32_t vr =
                        (uint32_t)((g * 64 + wn * 16 + nf * 8 + gid) * 128) + cx;
                    b[g][nf][0] = __float_as_uint(Bs[ vr       >> 2]);
                    b[g][nf][1] = __float_as_uint(Bs[(vr ^ 16) >> 2]);
                }
            #pragma unroll
            for (int i = 0; i < 4; i++)
                #pragma unroll
                for (int g = 0; g < 4; g++)
                    #pragma unroll
                    for (int nf = 0; nf < 2; nf++)
                        mma_tf32(acc[i][g][nf], a[i], b[g][nf]);
        }
    }

    // ---- fused epilogue (registers only) ----
    #pragma unroll
    for (int nf = 0; nf < 2; nf++) {
        const int jg = j0 + wn * 16 + nf * 8 + tg * 2;
        float bsum[4][2];
        #pragma unroll
        for (int g = 0; g < 4; g++)
            #pragma unroll
            for (int c = 0; c < 2; c++) {
                const int idx = g * NGATE + jg + c;
                bsum[g][c] = b_x[idx] + b_h[idx] + b_extra[idx];
            }

        #pragma unroll
        for (int i = 0; i < 4; i++) {
            #pragma unroll
            for (int h = 0; h < 2; h++) {
                const int mg = m0 + wm * 64 + i * 16 + gid + h * 8;
                const float2 cp = *reinterpret_cast<const float2*>(
                    c_prev + (size_t)mg * 1024 + jg);
                float ht[2], ct[2];
                #pragma unroll
                for (int c = 0; c < 2; c++) {
                    const int e = h * 2 + c;
                    const float fg = sigmoid_fast(acc[i][0][nf][e] + bsum[0][c]);
                    const float ig = sigmoid_fast(acc[i][1][nf][e] + bsum[1][c]);
                    const float og = sigmoid_fast(acc[i][2][nf][e] + bsum[2][c]);
                    const float cc = tanh_fast   (acc[i][3][nf][e] + bsum[3][c]);
                    const float cpv = (c == 0) ? cp.x : cp.y;
                    ct[c] = fg * cpv + ig * cc;
                    ht[c] = og * tanh_fast(ct[c]);
                }
                *reinterpret_cast<float2*>(out + (size_t)mg * 1024 + jg) =
                    make_float2(ht[0], ht[1]);
                *reinterpret_cast<float2*>(
                    out + (size_t)MB * 1024 + (size_t)mg * 1024 + jg) =
                    make_float2(ct[0], ct[1]);
            }
        }
    }
}

// ---------------- launch ----------------
extern "C" void kernel_launch(void* const* d_in, const int* in_sizes, int n_in,
                              void* d_out, int out_size) {
    const float* e_t     = (const float*)d_in[0];
    const float* h_prev  = (const float*)d_in[1];
    const float* c_prev  = (const float*)d_in[2];
    const float* W_x     = (const float*)d_in[3];
    const float* b_x     = (const float*)d_in[4];
    const float* W_h     = (const float*)d_in[5];
    const float* b_h     = (const float*)d_in[6];
    const float* b_extra = (const float*)d_in[7];
    float* out = (float*)d_out;

    cudaFuncSetAttribute(lstm_mma_kernel,
                         cudaFuncAttributeMaxDynamicSharedMemorySize, SMEM_DYN);

    dim3 grid(NGATE / NJ, MB / BM);   // (16, 64)
    lstm_mma_kernel<<<grid, THREADS, SMEM_DYN>>>(
        e_t, h_prev, c_prev, W_x, b_x, W_h, b_h, b_extra, out);
}

// round 9
// speedup vs baseline: 1.0139x; 1.0139x over previous
#include <cuda_runtime.h>
#include <cstdint>

// ---------------- problem / tile constants ----------------
#define MB      8192
#define NGATE   1024
#define BM      128          // CTA M tile
#define NJ      32           // gate-local cols per CTA (virtual N = 128)
#define BK      32           // K per stage
#define NKT     64           // 2048 / 32
#define STAGES  3
#define THREADS 256

#define STAGE_FLOATS (2 * 128 * 32)                // A(128x32)+B(128x32) = 8192 floats
#define SMEM_DYN     (STAGES * STAGE_FLOATS * 4)   // 98304 B

__device__ __forceinline__ uint32_t smem_u32(const void* p) {
    return (uint32_t)__cvta_generic_to_shared(p);
}
__device__ __forceinline__ void cp16(uint32_t dst, const void* src) {
    asm volatile("cp.async.cg.shared.global [%0], [%1], 16;\n" :: "r"(dst), "l"(src));
}
__device__ __forceinline__ void cp_commit() { asm volatile("cp.async.commit_group;\n"); }
template <int N>
__device__ __forceinline__ void cp_wait() {
    asm volatile("cp.async.wait_group %0;\n" :: "n"(N));
}
__device__ __forceinline__ uint32_t sw128(uint32_t off) {
    return off ^ ((off >> 3) & 0x70);
}
__device__ __forceinline__ void mma_tf32(float* d, const uint32_t* a, const uint32_t* b) {
    asm volatile(
        "mma.sync.aligned.m16n8k8.row.col.f32.tf32.tf32.f32 "
        "{%0,%1,%2,%3}, {%4,%5,%6,%7}, {%8,%9}, {%0,%1,%2,%3};"
        : "+f"(d[0]), "+f"(d[1]), "+f"(d[2]), "+f"(d[3])
        : "r"(a[0]), "r"(a[1]), "r"(a[2]), "r"(a[3]), "r"(b[0]), "r"(b[1]));
}
__device__ __forceinline__ float tanh_fast(float x) {
    float y;
    asm("tanh.approx.f32 %0, %1;" : "=f"(y) : "f"(x));
    return y;
}
__device__ __forceinline__ float sigmoid_fast(float x) {
    return 0.5f * tanh_fast(0.5f * x) + 0.5f;
}

// ---------------- kernel ----------------
// CTA: 128 rows x 32 gate-local cols of all 4 gates (virtual 128x128).
// Warp grid 2(m) x 4(n): warp tile 64 rows x 8 gate-local cols (32 virtual).
// Single __syncthreads per ktile: top-of-loop sync orders both "stage kt data
// visible" (after cp_wait) and "stage (kt+2)%3 reads from iter kt-1 finished"
// before the prefetch overwrites it.
__global__ void __launch_bounds__(THREADS, 2)
lstm_mma_kernel(const float* __restrict__ e_t,
                const float* __restrict__ h_prev,
                const float* __restrict__ c_prev,
                const float* __restrict__ W_x,
                const float* __restrict__ b_x,
                const float* __restrict__ W_h,
                const float* __restrict__ b_h,
                const float* __restrict__ b_extra,
                float* __restrict__ out)
{
    extern __shared__ float smf[];

    const int tid  = threadIdx.x;
    const int warp = tid >> 5;
    const int lane = tid & 31;
    const int gid  = lane >> 2;     // group id 0..7
    const int tg   = lane & 3;      // thread-in-group
    const int wm   = warp >> 2;     // 0..1 -> rows wm*64
    const int wn   = warp & 3;      // 0..3 -> gate-local cols wn*8
    const int m0   = blockIdx.y * BM;
    const int j0   = blockIdx.x * NJ;

    auto load_stage = [&](int kt, int stg) {
        const int kk = kt * BK;
        const float* __restrict__ Asrc = (kk < 1024) ? e_t : h_prev;
        const float* __restrict__ Wsrc = (kk < 1024) ? W_x : W_h;
        const int kloc = kk & 1023;
        const uint32_t As = smem_u32(smf + stg * STAGE_FLOATS);
        const uint32_t Bs = As + 128 * 128;     // A tile = 16 KB
        #pragma unroll
        for (int i = 0; i < 4; i++) {
            int c = tid + i * THREADS;
            int row = c >> 3, c16 = c & 7;
            cp16(As + sw128((uint32_t)(row * 128 + c16 * 16)),
                 Asrc + (size_t)(m0 + row) * 1024 + kloc + c16 * 4);
        }
        #pragma unroll
        for (int i = 0; i < 4; i++) {
            int c = tid + i * THREADS;
            int vr = c >> 3, c16 = c & 7;
            int g = vr >> 5, l = vr & 31;
            cp16(Bs + sw128((uint32_t)(vr * 128 + c16 * 16)),
                 Wsrc + (size_t)(g * NGATE + j0 + l) * 1024 + kloc + c16 * 4);
        }
    };

    float acc[4][4][4];   // [m_frag][gate][elem]
    #pragma unroll
    for (int i = 0; i < 4; i++)
        #pragma unroll
        for (int g = 0; g < 4; g++)
            #pragma unroll
            for (int e = 0; e < 4; e++) acc[i][g][e] = 0.0f;

    load_stage(0, 0); cp_commit();
    load_stage(1, 1); cp_commit();

    const uint32_t key = (uint32_t)gid << 4;    // swizzle XOR key (bytes)

    for (int kt = 0; kt < NKT; kt++) {
        if (kt + 1 < NKT) cp_wait<1>(); else cp_wait<0>();
        __syncthreads();

        if (kt + 2 < NKT) {
            load_stage(kt + 2, (kt + 2) % STAGES);
            cp_commit();
        }

        const int stg = kt % STAGES;
        const float* As = smf + stg * STAGE_FLOATS;
        const float* Bs = As + 4096;   // floats

        #pragma unroll
        for (int ks = 0; ks < 4; ks++) {
            // R4-verified form: XOR applied to the full column offset.
            const uint32_t cx = ((uint32_t)(ks * 32 + tg * 4)) ^ key;
            uint32_t a[4][4], b[4][2];
            #pragma unroll
            for (int i = 0; i < 4; i++) {
                const uint32_t r0 = (uint32_t)((wm * 64 + i * 16 + gid) * 128) + cx;
                a[i][0] = __float_as_uint(As[ r0             >> 2]);
                a[i][1] = __float_as_uint(As[(r0 + 1024)     >> 2]);
                a[i][2] = __float_as_uint(As[(r0 ^ 16)       >> 2]);
                a[i][3] = __float_as_uint(As[((r0 + 1024) ^ 16) >> 2]);
            }
            #pragma unroll
            for (int g = 0; g < 4; g++) {
                const uint32_t vr = (uint32_t)((g * 32 + wn * 8 + gid) * 128) + cx;
                b[g][0] = __float_as_uint(Bs[ vr       >> 2]);
                b[g][1] = __float_as_uint(Bs[(vr ^ 16) >> 2]);
            }
            #pragma unroll
            for (int i = 0; i < 4; i++)
                #pragma unroll
                for (int g = 0; g < 4; g++)
                    mma_tf32(acc[i][g], a[i], b[g]);
        }
        // no trailing sync: next iteration's top sync protects stage reuse
    }

    // ---- fused epilogue (registers only) ----
    const int jg = j0 + wn * 8 + tg * 2;
    float bsum[4][2];
    #pragma unroll
    for (int g = 0; g < 4; g++)
        #pragma unroll
        for (int c = 0; c < 2; c++) {
            const int idx = g * NGATE + jg + c;
            bsum[g][c] = b_x[idx] + b_h[idx] + b_extra[idx];
        }

    #pragma unroll
    for (int i = 0; i < 4; i++) {
        #pragma unroll
        for (int h = 0; h < 2; h++) {
            const int mg = m0 + wm * 64 + i * 16 + gid + h * 8;
            const float2 cp = *reinterpret_cast<const float2*>(
                c_prev + (size_t)mg * 1024 + jg);
            float ht[2], ct[2];
            #pragma unroll
            for (int c = 0; c < 2; c++) {
                const int e = h * 2 + c;
                const float fg = sigmoid_fast(acc[i][0][e] + bsum[0][c]);
                const float ig = sigmoid_fast(acc[i][1][e] + bsum[1][c]);
                const float og = sigmoid_fast(acc[i][2][e] + bsum[2][c]);
                const float cc = tanh_fast   (acc[i][3][e] + bsum[3][c]);
                const float cpv = (c == 0) ? cp.x : cp.y;
                ct[c] = fg * cpv + ig * cc;
                ht[c] = og * tanh_fast(ct[c]);
            }
            *reinterpret_cast<float2*>(out + (size_t)mg * 1024 + jg) =
                make_float2(ht[0], ht[1]);
            *reinterpret_cast<float2*>(
                out + (size_t)MB * 1024 + (size_t)mg * 1024 + jg) =
                make_float2(ct[0], ct[1]);
        }
    }
}

// ---------------- launch ----------------
extern "C" void kernel_launch(void* const* d_in, const int* in_sizes, int n_in,
                              void* d_out, int out_size) {
    const float* e_t     = (const float*)d_in[0];
    const float* h_prev  = (const float*)d_in[1];
    const float* c_prev  = (const float*)d_in[2];
    const float* W_x     = (const float*)d_in[3];
    const float* b_x     = (const float*)d_in[4];
    const float* W_h     = (const float*)d_in[5];
    const float* b_h     = (const float*)d_in[6];
    const float* b_extra = (const float*)d_in[7];
    float* out = (float*)d_out;

    cudaFuncSetAttribute(lstm_mma_kernel,
                         cudaFuncAttributeMaxDynamicSharedMemorySize, SMEM_DYN);

    dim3 grid(NGATE / NJ, MB / BM);   // (32, 64)
    lstm_mma_kernel<<<grid, THREADS, SMEM_DYN>>>(
        e_t, h_prev, c_prev, W_x, b_x, W_h, b_h, b_extra, out);
}

// round 11
// speedup vs baseline: 1.7594x; 1.7354x over previous
#include <cuda_runtime.h>
#include <cuda_fp16.h>
#include <cstdint>

// ---------------- problem / tile constants ----------------
#define MB      8192
#define NGATE   1024
#define BM      128          // CTA M tile
#define NJ      32           // gate-local cols per CTA (virtual N = 128)
#define BK      64           // K halves per stage (64 fp16 = 128 B row)
#define NKT     32           // 2048 / 64
#define STAGES  3
#define THREADS 256

#define A_STAGE_BYTES (128 * 128)                  // 16 KB
#define B_STAGE_BYTES (128 * 128)                  // 16 KB
#define STAGE_BYTES   (A_STAGE_BYTES + B_STAGE_BYTES)   // 32 KB
#define SMEM_DYN      (STAGES * STAGE_BYTES)       // 98304 B

// fp16 scratch: [e_t 8M][h_prev 8M][W_x 4M][W_h 4M] halves = 48 MB
#define E_OFF  0u
#define H_OFF  8388608u
#define WX_OFF 16777216u
#define WH_OFF 20971520u
__device__ __align__(16) __half g_fp16[25165824];

// ---------------- helpers ----------------
__device__ __forceinline__ uint32_t smem_u32(const void* p) {
    return (uint32_t)__cvta_generic_to_shared(p);
}
__device__ __forceinline__ void cp16(uint32_t dst, const void* src) {
    asm volatile("cp.async.cg.shared.global [%0], [%1], 16;\n" :: "r"(dst), "l"(src));
}
__device__ __forceinline__ void cp_commit() { asm volatile("cp.async.commit_group;\n"); }
template <int N>
__device__ __forceinline__ void cp_wait() {
    asm volatile("cp.async.wait_group %0;\n" :: "n"(N));
}
__device__ __forceinline__ uint32_t sw128(uint32_t off) {
    return off ^ ((off >> 3) & 0x70);
}
__device__ __forceinline__ void mma_f16(float* d, const uint32_t* a, const uint32_t* b) {
    asm volatile(
        "mma.sync.aligned.m16n8k16.row.col.f32.f16.f16.f32 "
        "{%0,%1,%2,%3}, {%4,%5,%6,%7}, {%8,%9}, {%0,%1,%2,%3};"
        : "+f"(d[0]), "+f"(d[1]), "+f"(d[2]), "+f"(d[3])
        : "r"(a[0]), "r"(a[1]), "r"(a[2]), "r"(a[3]), "r"(b[0]), "r"(b[1]));
}
__device__ __forceinline__ float tanh_fast(float x) {
    float y;
    asm("tanh.approx.f32 %0, %1;" : "=f"(y) : "f"(x));
    return y;
}
__device__ __forceinline__ float sigmoid_fast(float x) {
    return 0.5f * tanh_fast(0.5f * x) + 0.5f;
}

// ---------------- fp32 -> fp16 conversion pass ----------------
__global__ void __launch_bounds__(256, 8)
convert_kernel(const float* __restrict__ src, uint32_t dst_off, int n4) {
    __half* __restrict__ dst = g_fp16 + dst_off;
    const int stride = gridDim.x * blockDim.x;
    for (int i = blockIdx.x * blockDim.x + threadIdx.x; i < n4; i += stride) {
        const float4 v = reinterpret_cast<const float4*>(src)[i];
        __half2 lo = __floats2half2_rn(v.x, v.y);
        __half2 hi = __floats2half2_rn(v.z, v.w);
        reinterpret_cast<__half2*>(dst)[i * 2]     = lo;
        reinterpret_cast<__half2*>(dst)[i * 2 + 1] = hi;
    }
}

// ---------------- main fused LSTM kernel (fp16 MMA, f32 accum) ----------------
// CTA: 128 rows x 32 gate-local cols of all 4 gates (virtual 128x128).
// Warp grid 2(m) x 4(n): warp tile 64 rows x 8 gate-local cols.
// smem rows are 128 B = 64 fp16; address math identical to the proven tf32 kernel.
__global__ void __launch_bounds__(THREADS, 2)
lstm_mma_kernel(const float* __restrict__ c_prev,
                const float* __restrict__ b_x,
                const float* __restrict__ b_h,
                const float* __restrict__ b_extra,
                float* __restrict__ out)
{
    extern __shared__ char smb[];

    const int tid  = threadIdx.x;
    const int warp = tid >> 5;
    const int lane = tid & 31;
    const int gid  = lane >> 2;     // group id 0..7
    const int tg   = lane & 3;      // thread-in-group
    const int wm   = warp >> 2;     // 0..1 -> rows wm*64
    const int wn   = warp & 3;      // 0..3 -> gate-local cols wn*8
    const int m0   = blockIdx.y * BM;
    const int j0   = blockIdx.x * NJ;

    const __half* __restrict__ Eh = g_fp16 + E_OFF;   // [8192][1024]
    const __half* __restrict__ Hh = g_fp16 + H_OFF;   // [8192][1024]
    const __half* __restrict__ Wx = g_fp16 + WX_OFF;  // [4096][1024]
    const __half* __restrict__ Wh = g_fp16 + WH_OFF;  // [4096][1024]

    auto load_stage = [&](int kt, int stg) {
        const int kk = kt * BK;                        // half index in [0,2048)
        const __half* __restrict__ Asrc = (kk < 1024) ? Eh : Hh;
        const __half* __restrict__ Wsrc = (kk < 1024) ? Wx : Wh;
        const int kloc = kk & 1023;
        const uint32_t As = smem_u32(smb + stg * STAGE_BYTES);
        const uint32_t Bs = As + A_STAGE_BYTES;
        // A: 128 rows x 8 x 16B chunks (8 halves each) -> 4 per thread
        #pragma unroll
        for (int i = 0; i < 4; i++) {
            int c = tid + i * THREADS;
            int row = c >> 3, c16 = c & 7;
            cp16(As + sw128((uint32_t)(row * 128 + c16 * 16)),
                 Asrc + (size_t)(m0 + row) * 1024 + kloc + c16 * 8);
        }
        // B: 128 vrows (vr = g*32 + l) x 8 x 16B -> 4 per thread
        #pragma unroll
        for (int i = 0; i < 4; i++) {
            int c = tid + i * THREADS;
            int vr = c >> 3, c16 = c & 7;
            int g = vr >> 5, l = vr & 31;
            cp16(Bs + sw128((uint32_t)(vr * 128 + c16 * 16)),
                 Wsrc + (size_t)(g * NGATE + j0 + l) * 1024 + kloc + c16 * 8);
        }
    };

    float acc[4][4][4];   // [m_frag][gate][elem]
    #pragma unroll
    for (int i = 0; i < 4; i++)
        #pragma unroll
        for (int g = 0; g < 4; g++)
            #pragma unroll
            for (int e = 0; e < 4; e++) acc[i][g][e] = 0.0f;

    load_stage(0, 0); cp_commit();
    load_stage(1, 1); cp_commit();

    const uint32_t key = (uint32_t)gid << 4;    // swizzle XOR key (bytes)

    for (int kt = 0; kt < NKT; kt++) {
        if (kt + 1 < NKT) cp_wait<1>(); else cp_wait<0>();
        __syncthreads();      // stage kt visible; stage (kt+2)%3 reads retired

        if (kt + 2 < NKT) {
            load_stage(kt + 2, (kt + 2) % STAGES);
            cp_commit();
        }

        const int stg = kt % STAGES;
        const char* As = smb + stg * STAGE_BYTES;
        const char* Bs = As + A_STAGE_BYTES;

        #pragma unroll
        for (int ks = 0; ks < 4; ks++) {        // 4 x K=16 halves per 64-half stage
            // ks*16 halves = 32 B stride; tg*2 halves = 4 B — same math as tf32 kernel
            const uint32_t cx = ((uint32_t)(ks * 32 + tg * 4)) ^ key;
            uint32_t a[4][4], b[4][2];
            #pragma unroll
            for (int i = 0; i < 4; i++) {
                const uint32_t r0 = (uint32_t)((wm * 64 + i * 16 + gid) * 128) + cx;
                a[i][0] = *reinterpret_cast<const uint32_t*>(As + r0);            // row g,   k..k+1
                a[i][1] = *reinterpret_cast<const uint32_t*>(As + r0 + 1024);     // row g+8
                a[i][2] = *reinterpret_cast<const uint32_t*>(As + (r0 ^ 16));     // row g,   k+8..k+9
                a[i][3] = *reinterpret_cast<const uint32_t*>(As + ((r0 + 1024) ^ 16));
            }
            #pragma unroll
            for (int g = 0; g < 4; g++) {
                const uint32_t vr = (uint32_t)((g * 32 + wn * 8 + gid) * 128) + cx;
                b[g][0] = *reinterpret_cast<const uint32_t*>(Bs + vr);            // col g, k..k+1
                b[g][1] = *reinterpret_cast<const uint32_t*>(Bs + (vr ^ 16));     // col g, k+8..k+9
            }
            #pragma unroll
            for (int i = 0; i < 4; i++)
                #pragma unroll
                for (int g = 0; g < 4; g++)
                    mma_f16(acc[i][g], a[i], b[g]);
        }
        // next iteration's top sync protects stage reuse
    }

    // ---- fused epilogue (registers only) ----
    const int jg = j0 + wn * 8 + tg * 2;
    float bsum[4][2];
    #pragma unroll
    for (int g = 0; g < 4; g++)
        #pragma unroll
        for (int c = 0; c < 2; c++) {
            const int idx = g * NGATE + jg + c;
            bsum[g][c] = b_x[idx] + b_h[idx] + b_extra[idx];
        }

    #pragma unroll
    for (int i = 0; i < 4; i++) {
        #pragma unroll
        for (int h = 0; h < 2; h++) {
            const int mg = m0 + wm * 64 + i * 16 + gid + h * 8;
            const float2 cp = *reinterpret_cast<const float2*>(
                c_prev + (size_t)mg * 1024 + jg);
            float ht[2], ct[2];
            #pragma unroll
            for (int c = 0; c < 2; c++) {
                const int e = h * 2 + c;
                const float fg = sigmoid_fast(acc[i][0][e] + bsum[0][c]);
                const float ig = sigmoid_fast(acc[i][1][e] + bsum[1][c]);
                const float og = sigmoid_fast(acc[i][2][e] + bsum[2][c]);
                const float cc = tanh_fast   (acc[i][3][e] + bsum[3][c]);
                const float cpv = (c == 0) ? cp.x : cp.y;
                ct[c] = fg * cpv + ig * cc;
                ht[c] = og * tanh_fast(ct[c]);
            }
            *reinterpret_cast<float2*>(out + (size_t)mg * 1024 + jg) =
                make_float2(ht[0], ht[1]);
            *reinterpret_cast<float2*>(
                out + (size_t)MB * 1024 + (size_t)mg * 1024 + jg) =
                make_float2(ct[0], ct[1]);
        }
    }
}

// ---------------- launch ----------------
extern "C" void kernel_launch(void* const* d_in, const int* in_sizes, int n_in,
                              void* d_out, int out_size) {
    const float* e_t     = (const float*)d_in[0];
    const float* h_prev  = (const float*)d_in[1];
    const float* c_prev  = (const float*)d_in[2];
    const float* W_x     = (const float*)d_in[3];
    const float* b_x     = (const float*)d_in[4];
    const float* W_h     = (const float*)d_in[5];
    const float* b_h     = (const float*)d_in[6];
    const float* b_extra = (const float*)d_in[7];
    float* out = (float*)d_out;

    cudaFuncSetAttribute(lstm_mma_kernel,
                         cudaFuncAttributeMaxDynamicSharedMemorySize, SMEM_DYN);

    // pass 1: fp32 -> fp16 scratch
    convert_kernel<<<4096, 256>>>(e_t,    E_OFF,  (8192 * 1024) / 4);
    convert_kernel<<<4096, 256>>>(h_prev, H_OFF,  (8192 * 1024) / 4);
    convert_kernel<<<2048, 256>>>(W_x,    WX_OFF, (4096 * 1024) / 4);
    convert_kernel<<<2048, 256>>>(W_h,    WH_OFF, (4096 * 1024) / 4);

    // pass 2: fused GEMM + gates
    dim3 grid(NGATE / NJ, MB / BM);   // (32, 64)
    lstm_mma_kernel<<<grid, THREADS, SMEM_DYN>>>(
        c_prev, b_x, b_h, b_extra, out);
}

// round 13
// speedup vs baseline: 1.9323x; 1.0982x over previous
#include <cuda_runtime.h>
#include <cuda_fp16.h>
#include <cstdint>

// ---------------- problem / tile constants ----------------
#define MB      8192
#define NGATE   1024
#define BM      128          // CTA M tile
#define NJ      32           // gate-local cols per CTA (virtual N = 128)
#define BK      64           // K halves per stage (64 fp16 = 128 B row)
#define NKT     32           // 2048 / 64
#define STAGES  3
#define THREADS 256

#define A_STAGE_BYTES (128 * 128)                  // 16 KB
#define B_STAGE_BYTES (128 * 128)                  // 16 KB
#define STAGE_BYTES   (A_STAGE_BYTES + B_STAGE_BYTES)   // 32 KB
#define SMEM_DYN      (STAGES * STAGE_BYTES)       // 98304 B

// fp16 scratch: [e_t 8M][h_prev 8M][W_x 4M][W_h 4M] halves = 48 MB
#define E_OFF  0u
#define H_OFF  8388608u
#define WX_OFF 16777216u
#define WH_OFF 20971520u
__device__ __align__(16) __half g_fp16[25165824];

// ---------------- helpers ----------------
__device__ __forceinline__ uint32_t smem_u32(const void* p) {
    return (uint32_t)__cvta_generic_to_shared(p);
}
__device__ __forceinline__ void cp16(uint32_t dst, const void* src) {
    asm volatile("cp.async.cg.shared.global [%0], [%1], 16;\n" :: "r"(dst), "l"(src));
}
__device__ __forceinline__ void cp_commit() { asm volatile("cp.async.commit_group;\n"); }
template <int N>
__device__ __forceinline__ void cp_wait() {
    asm volatile("cp.async.wait_group %0;\n" :: "n"(N));
}
__device__ __forceinline__ uint32_t sw128(uint32_t off) {
    return off ^ ((off >> 3) & 0x70);
}
__device__ __forceinline__ void ldsm_x4(uint32_t* r, uint32_t addr) {
    asm volatile("ldmatrix.sync.aligned.m8n8.x4.shared.b16 {%0,%1,%2,%3}, [%4];"
                 : "=r"(r[0]), "=r"(r[1]), "=r"(r[2]), "=r"(r[3]) : "r"(addr));
}
__device__ __forceinline__ void ldsm_x2(uint32_t* r, uint32_t addr) {
    // NON-trans: smem tile is [n][k] (k contiguous); plain ldmatrix yields the
    // mma B fragment (lane l -> n=l/4, k=(l%4)*2,+1). .trans here was the R12 bug.
    asm volatile("ldmatrix.sync.aligned.m8n8.x2.shared.b16 {%0,%1}, [%2];"
                 : "=r"(r[0]), "=r"(r[1]) : "r"(addr));
}
__device__ __forceinline__ void mma_f16(float* d, const uint32_t* a, const uint32_t* b) {
    asm volatile(
        "mma.sync.aligned.m16n8k16.row.col.f32.f16.f16.f32 "
        "{%0,%1,%2,%3}, {%4,%5,%6,%7}, {%8,%9}, {%0,%1,%2,%3};"
        : "+f"(d[0]), "+f"(d[1]), "+f"(d[2]), "+f"(d[3])
        : "r"(a[0]), "r"(a[1]), "r"(a[2]), "r"(a[3]), "r"(b[0]), "r"(b[1]));
}
__device__ __forceinline__ float tanh_fast(float x) {
    float y;
    asm("tanh.approx.f32 %0, %1;" : "=f"(y) : "f"(x));
    return y;
}
__device__ __forceinline__ float sigmoid_fast(float x) {
    return 0.5f * tanh_fast(0.5f * x) + 0.5f;
}

// ---------------- fused fp32 -> fp16 conversion (single launch) ----------------
__global__ void __launch_bounds__(256, 8)
convert_all_kernel(const float* __restrict__ e_t, const float* __restrict__ h_prev,
                   const float* __restrict__ W_x, const float* __restrict__ W_h) {
    const int n4 = 6 * 1024 * 1024;
    const int stride = gridDim.x * blockDim.x;
    for (int i = blockIdx.x * blockDim.x + threadIdx.x; i < n4; i += stride) {
        const float* src;
        int base;
        if (i < 2097152)      { src = e_t;    base = 0; }
        else if (i < 4194304) { src = h_prev; base = 2097152; }
        else if (i < 5242880) { src = W_x;    base = 4194304; }
        else                  { src = W_h;    base = 5242880; }
        const float4 v = reinterpret_cast<const float4*>(src)[i - base];
        __half2 lo = __floats2half2_rn(v.x, v.y);
        __half2 hi = __floats2half2_rn(v.z, v.w);
        reinterpret_cast<__half2*>(g_fp16)[i * 2]     = lo;
        reinterpret_cast<__half2*>(g_fp16)[i * 2 + 1] = hi;
    }
}

// ---------------- main fused LSTM kernel (fp16 MMA, f32 accum, ldmatrix) ----------------
__global__ void __launch_bounds__(THREADS, 2)
lstm_mma_kernel(const float* __restrict__ c_prev,
                const float* __restrict__ b_x,
                const float* __restrict__ b_h,
                const float* __restrict__ b_extra,
                float* __restrict__ out)
{
    extern __shared__ char smb[];

    const int tid  = threadIdx.x;
    const int warp = tid >> 5;
    const int lane = tid & 31;
    const int gid  = lane >> 2;     // group id 0..7
    const int tg   = lane & 3;      // thread-in-group
    const int wm   = warp >> 2;     // 0..1 -> rows wm*64
    const int wn   = warp & 3;      // 0..3 -> gate-local cols wn*8
    const int m0   = blockIdx.y * BM;
    const int j0   = blockIdx.x * NJ;

    const __half* __restrict__ Eh = g_fp16 + E_OFF;
    const __half* __restrict__ Hh = g_fp16 + H_OFF;
    const __half* __restrict__ Wx = g_fp16 + WX_OFF;
    const __half* __restrict__ Wh = g_fp16 + WH_OFF;

    auto load_stage = [&](int kt, int stg) {
        const int kk = kt * BK;
        const __half* __restrict__ Asrc = (kk < 1024) ? Eh : Hh;
        const __half* __restrict__ Wsrc = (kk < 1024) ? Wx : Wh;
        const int kloc = kk & 1023;
        const uint32_t As = smem_u32(smb + stg * STAGE_BYTES);
        const uint32_t Bs = As + A_STAGE_BYTES;
        #pragma unroll
        for (int i = 0; i < 4; i++) {
            int c = tid + i * THREADS;
            int row = c >> 3, c16 = c & 7;
            cp16(As + sw128((uint32_t)(row * 128 + c16 * 16)),
                 Asrc + (size_t)(m0 + row) * 1024 + kloc + c16 * 8);
        }
        #pragma unroll
        for (int i = 0; i < 4; i++) {
            int c = tid + i * THREADS;
            int vr = c >> 3, c16 = c & 7;
            int g = vr >> 5, l = vr & 31;
            cp16(Bs + sw128((uint32_t)(vr * 128 + c16 * 16)),
                 Wsrc + (size_t)(g * NGATE + j0 + l) * 1024 + kloc + c16 * 8);
        }
    };

    float acc[4][4][4];   // [m_frag][gate][elem]
    #pragma unroll
    for (int i = 0; i < 4; i++)
        #pragma unroll
        for (int g = 0; g < 4; g++)
            #pragma unroll
            for (int e = 0; e < 4; e++) acc[i][g][e] = 0.0f;

    load_stage(0, 0); cp_commit();
    load_stage(1, 1); cp_commit();

    // ---- per-lane ldmatrix base addresses (stage-relative, bytes) ----
    // A (x4): tile0 -> a0 (rows +0, k+0), tile1 -> a1 (rows +8, k+0),
    //         tile2 -> a2 (rows +0, k+8), tile3 -> a3 (rows +8, k+8).
    // addr = base ^ (ks*32); base = row*128 + (kofs ^ ((row&7)<<4))
    uint32_t a_base[4];
    {
        const int tilesel = lane >> 3;
        const int rin     = lane & 7;
        const int radd    = (tilesel & 1) ? 8 : 0;
        const uint32_t kofs = (tilesel >= 2) ? 16u : 0u;
        const uint32_t key  = (uint32_t)rin << 4;
        #pragma unroll
        for (int i = 0; i < 4; i++) {
            const int trow = wm * 64 + i * 16 + radd + rin;
            a_base[i] = (uint32_t)(trow * 128) + (kofs ^ key);
        }
    }
    // B (x2, non-trans): lanes 0-7 -> b0 tile (n rows +0..7, k+0),
    //                    lanes 8-15 -> b1 tile (same n rows, k+8).
    uint32_t b_base[4];
    {
        const int rin  = lane & 7;
        const uint32_t kofs = ((lane >> 3) & 1) ? 16u : 0u;
        const uint32_t key  = (uint32_t)rin << 4;
        #pragma unroll
        for (int g = 0; g < 4; g++) {
            const int nrow = g * 32 + wn * 8 + rin;
            b_base[g] = (uint32_t)(nrow * 128) + (kofs ^ key);
        }
    }

    for (int kt = 0; kt < NKT; kt++) {
        if (kt + 1 < NKT) cp_wait<1>(); else cp_wait<0>();
        __syncthreads();

        if (kt + 2 < NKT) {
            load_stage(kt + 2, (kt + 2) % STAGES);
            cp_commit();
        }

        const int stg = kt % STAGES;
        const uint32_t As = smem_u32(smb) + (uint32_t)(stg * STAGE_BYTES);
        const uint32_t Bs = As + A_STAGE_BYTES;

        #pragma unroll
        for (int ks = 0; ks < 4; ks++) {
            const uint32_t kx = (uint32_t)(ks * 32);
            uint32_t a[4][4], b[4][2];
            #pragma unroll
            for (int i = 0; i < 4; i++)
                ldsm_x4(a[i], (As + a_base[i]) ^ kx);
            #pragma unroll
            for (int g = 0; g < 4; g++)
                ldsm_x2(b[g], (Bs + b_base[g]) ^ kx);
            #pragma unroll
            for (int i = 0; i < 4; i++)
                #pragma unroll
                for (int g = 0; g < 4; g++)
                    mma_f16(acc[i][g], a[i], b[g]);
        }
    }

    // ---- fused epilogue (registers only) ----
    const int jg = j0 + wn * 8 + tg * 2;
    float bsum[4][2];
    #pragma unroll
    for (int g = 0; g < 4; g++)
        #pragma unroll
        for (int c = 0; c < 2; c++) {
            const int idx = g * NGATE + jg + c;
            bsum[g][c] = b_x[idx] + b_h[idx] + b_extra[idx];
        }

    #pragma unroll
    for (int i = 0; i < 4; i++) {
        #pragma unroll
        for (int h = 0; h < 2; h++) {
            const int mg = m0 + wm * 64 + i * 16 + gid + h * 8;
            const float2 cp = *reinterpret_cast<const float2*>(
                c_prev + (size_t)mg * 1024 + jg);
            float ht[2], ct[2];
            #pragma unroll
            for (int c = 0; c < 2; c++) {
                const int e = h * 2 + c;
                const float fg = sigmoid_fast(acc[i][0][e] + bsum[0][c]);
                const float ig = sigmoid_fast(acc[i][1][e] + bsum[1][c]);
                const float og = sigmoid_fast(acc[i][2][e] + bsum[2][c]);
                const float cc = tanh_fast   (acc[i][3][e] + bsum[3][c]);
                const float cpv = (c == 0) ? cp.x : cp.y;
                ct[c] = fg * cpv + ig * cc;
                ht[c] = og * tanh_fast(ct[c]);
            }
            *reinterpret_cast<float2*>(out + (size_t)mg * 1024 + jg) =
                make_float2(ht[0], ht[1]);
            *reinterpret_cast<float2*>(
                out + (size_t)MB * 1024 + (size_t)mg * 1024 + jg) =
                make_float2(ct[0], ct[1]);
        }
    }
}

// ---------------- launch ----------------
extern "C" void kernel_launch(void* const* d_in, const int* in_sizes, int n_in,
                              void* d_out, int out_size) {
    const float* e_t     = (const float*)d_in[0];
    const float* h_prev  = (const float*)d_in[1];
    const float* c_prev  = (const float*)d_in[2];
    const float* W_x     = (const float*)d_in[3];
    const float* b_x     = (const float*)d_in[4];
    const float* W_h     = (const float*)d_in[5];
    const float* b_h     = (const float*)d_in[6];
    const float* b_extra = (const float*)d_in[7];
    float* out = (float*)d_out;

    cudaFuncSetAttribute(lstm_mma_kernel,
                         cudaFuncAttributeMaxDynamicSharedMemorySize, SMEM_DYN);

    convert_all_kernel<<<4736, 256>>>(e_t, h_prev, W_x, W_h);

    dim3 grid(NGATE / NJ, MB / BM);   // (32, 64)
    lstm_mma_kernel<<<grid, THREADS, SMEM_DYN>>>(
        c_prev, b_x, b_h, b_extra, out);
}